// round 2
// baseline (speedup 1.0000x reference)
#include <cuda_runtime.h>
#include <math.h>

#define BATCH 16
#define HH 1024
#define WW 1024
#define TILE_X 32
#define TILE_Y 16
#define HALO 2
#define SMX (TILE_X + 2*HALO)   // 36
#define SMY (TILE_Y + 2*HALO)   // 20
#define NTHREADS (TILE_X * TILE_Y)

// Scratch: blurred grayscale field g [B,H,W]
__device__ float g_buf[BATCH * HH * WW];
// Per-batch running max of s (as float bits; s >= 0 so int-compare == float-compare)
__device__ int g_max_bits[BATCH];
// Per-batch gamma after the all-zero fallback
__device__ float g_gamma[BATCH];

__global__ void reset_kernel() {
    int i = threadIdx.x;
    if (i < BATCH) g_max_bits[i] = 0;
}

// ---------------------------------------------------------------------------
// K1: grayscale + separable 5-tap Gaussian blur (SAME, zero padding)
// ---------------------------------------------------------------------------
__global__ void blur_kernel(const float* __restrict__ x,
                            const float* __restrict__ to_gray) {
    __shared__ float gt[SMY][SMX];   // grayscale tile with halo
    __shared__ float ht[SMY][TILE_X]; // horizontally blurred

    const int b  = blockIdx.z;
    const int bx = blockIdx.x * TILE_X;
    const int by = blockIdx.y * TILE_Y;
    const int tx = threadIdx.x;
    const int ty = threadIdx.y;
    const int tid = ty * TILE_X + tx;

    const float c0 = to_gray[0], c1 = to_gray[1], c2 = to_gray[2];

    // 1D Gaussian weights, normalized by sum(g) (fp32, matching reference)
    float w[5];
    {
        float sum = 0.0f;
        #pragma unroll
        for (int i = 0; i < 5; i++) {
            float ax = (float)i - 2.0f;
            w[i] = expf(-0.5f * ax * ax / (10.0f * 10.0f));
            sum += w[i];
        }
        #pragma unroll
        for (int i = 0; i < 5; i++) w[i] /= sum;
    }

    // Load grayscale tile (zero outside image — SAME conv zero-pads)
    const float* xb = x + (size_t)b * 3 * HH * WW;
    for (int idx = tid; idx < SMY * SMX; idx += NTHREADS) {
        int r = idx / SMX, c = idx % SMX;
        int gi = by + r - HALO;
        int gj = bx + c - HALO;
        float v = 0.0f;
        if (gi >= 0 && gi < HH && gj >= 0 && gj < WW) {
            size_t off = (size_t)gi * WW + gj;
            v = c0 * xb[off] + c1 * xb[off + (size_t)HH * WW]
                            + c2 * xb[off + 2 * (size_t)HH * WW];
        }
        gt[r][c] = v;
    }
    __syncthreads();

    // Horizontal pass: ht[r][tx] = sum_d w[d]*gt[r][tx+d]  (center at tx+2)
    for (int r = ty; r < SMY; r += TILE_Y) {
        float acc = 0.0f;
        #pragma unroll
        for (int d = 0; d < 5; d++) acc += w[d] * gt[r][tx + d];
        ht[r][tx] = acc;
    }
    __syncthreads();

    // Vertical pass
    float acc = 0.0f;
    #pragma unroll
    for (int d = 0; d < 5; d++) acc += w[d] * ht[ty + d][tx];

    g_buf[((size_t)b * HH + (by + ty)) * WW + (bx + tx)] = acc;
}

// ---------------------------------------------------------------------------
// Hessian from g tile (torch.gradient semantics: central interior, one-sided edges)
// t[ly+di][lx+dj] == g(gi+di, gj+dj) for di,dj in [-2,2] (clamped loads; clamped
// entries are only touched when the edge branches never read them)
// ---------------------------------------------------------------------------
__device__ __forceinline__ void hessian_at(const float t[SMY][SMX],
                                           int ly, int lx, int gi, int gj,
                                           float& h00, float& h01, float& h11) {
    #define G(di, dj) t[ly + (di)][lx + (dj)]

    // gx (d/drow) at row offset r, same column
    float gxm, gx0, gxp;
    {
        // r = -1, 0, +1
        int gr;
        gr = gi - 1;
        gxm = (gr == 0) ? (G(0,0) - G(-1,0))
            : (gi - 1 < 0) ? 0.0f
            : (gr == HH-1) ? (G(-1,0) - G(-2,0))
            : 0.5f * (G(0,0) - G(-2,0));
        gr = gi;
        gx0 = (gr == 0) ? (G(1,0) - G(0,0))
            : (gr == HH-1) ? (G(0,0) - G(-1,0))
            : 0.5f * (G(1,0) - G(-1,0));
        gr = gi + 1;
        gxp = (gr == 0) ? (G(2,0) - G(1,0))
            : (gr == HH-1) ? (G(1,0) - G(0,0))
            : (gi + 1 > HH-1) ? 0.0f
            : 0.5f * (G(2,0) - G(0,0));
    }
    h00 = (gi == 0) ? (gxp - gx0)
        : (gi == HH-1) ? (gx0 - gxm)
        : 0.5f * (gxp - gxm);

    // gx at column offsets -1, 0, +1 (row gradient evaluated at shifted column)
    float gxcm, gxc0, gxcp;
    {
        if (gi == 0) {
            gxcm = G(1,-1) - G(0,-1);
            gxc0 = G(1, 0) - G(0, 0);
            gxcp = G(1, 1) - G(0, 1);
        } else if (gi == HH-1) {
            gxcm = G(0,-1) - G(-1,-1);
            gxc0 = G(0, 0) - G(-1, 0);
            gxcp = G(0, 1) - G(-1, 1);
        } else {
            gxcm = 0.5f * (G(1,-1) - G(-1,-1));
            gxc0 = 0.5f * (G(1, 0) - G(-1, 0));
            gxcp = 0.5f * (G(1, 1) - G(-1, 1));
        }
    }
    h01 = (gj == 0) ? (gxcp - gxc0)
        : (gj == WW-1) ? (gxc0 - gxcm)
        : 0.5f * (gxcp - gxcm);

    // gy (d/dcol) at column offsets -1, 0, +1
    float gym, gy0, gyp;
    {
        int gc;
        gc = gj - 1;
        gym = (gc == 0) ? (G(0,0) - G(0,-1))
            : (gj - 1 < 0) ? 0.0f
            : (gc == WW-1) ? (G(0,-1) - G(0,-2))
            : 0.5f * (G(0,0) - G(0,-2));
        gc = gj;
        gy0 = (gc == 0) ? (G(0,1) - G(0,0))
            : (gc == WW-1) ? (G(0,0) - G(0,-1))
            : 0.5f * (G(0,1) - G(0,-1));
        gc = gj + 1;
        gyp = (gc == 0) ? (G(0,2) - G(0,1))
            : (gc == WW-1) ? (G(0,1) - G(0,0))
            : (gj + 1 > WW-1) ? 0.0f
            : 0.5f * (G(0,2) - G(0,0));
    }
    h11 = (gj == 0) ? (gyp - gy0)
        : (gj == WW-1) ? (gy0 - gym)
        : 0.5f * (gyp - gym);
    #undef G
}

__device__ __forceinline__ void load_g_tile(float t[SMY][SMX], int b, int bx, int by, int tid) {
    for (int idx = tid; idx < SMY * SMX; idx += NTHREADS) {
        int r = idx / SMX, c = idx % SMX;
        int gi = by + r - HALO; gi = gi < 0 ? 0 : (gi > HH-1 ? HH-1 : gi);
        int gj = bx + c - HALO; gj = gj < 0 ? 0 : (gj > WW-1 ? WW-1 : gj);
        t[r][c] = g_buf[((size_t)b * HH + gi) * WW + gj];
    }
}

// ---------------------------------------------------------------------------
// K2: s = ||eig||_2 per pixel, per-batch max via block reduce + atomicMax
// ---------------------------------------------------------------------------
__global__ void smax_kernel() {
    __shared__ float t[SMY][SMX];
    __shared__ float red[NTHREADS / 32];

    const int b  = blockIdx.z;
    const int bx = blockIdx.x * TILE_X;
    const int by = blockIdx.y * TILE_Y;
    const int tx = threadIdx.x, ty = threadIdx.y;
    const int tid = ty * TILE_X + tx;

    load_g_tile(t, b, bx, by, tid);
    __syncthreads();

    const int gi = by + ty, gj = bx + tx;
    float h00, h01, h11;
    hessian_at(t, ty + HALO, tx + HALO, gi, gj, h00, h01, h11);

    float mean = 0.5f * (h00 + h11);
    float dif  = 0.5f * (h00 - h11);
    float disc = sqrtf(dif * dif + h01 * h01);
    float e0 = mean - disc, e1 = mean + disc;
    float s = sqrtf(e0 * e0 + e1 * e1);

    // block max
    float v = s;
    #pragma unroll
    for (int off = 16; off > 0; off >>= 1)
        v = fmaxf(v, __shfl_xor_sync(0xffffffffu, v, off));
    if ((tid & 31) == 0) red[tid >> 5] = v;
    __syncthreads();
    if (tid == 0) {
        float m = red[0];
        #pragma unroll
        for (int i = 1; i < NTHREADS / 32; i++) m = fmaxf(m, red[i]);
        atomicMax(&g_max_bits[b], __float_as_int(m)); // m >= 0
    }
}

// ---------------------------------------------------------------------------
// K2b: gamma = max/2 per batch, all-zero => 1.0 everywhere
// ---------------------------------------------------------------------------
__global__ void gamma_kernel() {
    int i = threadIdx.x;
    float m = (i < BATCH) ? __int_as_float(g_max_bits[i]) : 0.0f;
    unsigned any = __ballot_sync(0xffffffffu, (i < BATCH) && (m != 0.0f));
    if (i < BATCH) g_gamma[i] = (any == 0u) ? 1.0f : 0.5f * m;
}

// ---------------------------------------------------------------------------
// K3: final response
// ---------------------------------------------------------------------------
__global__ void final_kernel(float* __restrict__ out) {
    __shared__ float t[SMY][SMX];

    const int b  = blockIdx.z;
    const int bx = blockIdx.x * TILE_X;
    const int by = blockIdx.y * TILE_Y;
    const int tx = threadIdx.x, ty = threadIdx.y;
    const int tid = ty * TILE_X + tx;

    load_g_tile(t, b, bx, by, tid);
    __syncthreads();

    const int gi = by + ty, gj = bx + tx;
    float h00, h01, h11;
    hessian_at(t, ty + HALO, tx + HALO, gi, gj, h00, h01, h11);

    float mean = 0.5f * (h00 + h11);
    float dif  = 0.5f * (h00 - h11);
    float disc = sqrtf(dif * dif + h01 * h01);
    float e0 = mean - disc, e1 = mean + disc;

    bool swap = fabsf(e1) < fabsf(e0);
    float lam1 = swap ? e1 : e0;
    float lam2 = fmaxf(swap ? e0 : e1, 1e-10f);
    float rb = fabsf(lam1) / lam2;
    float s  = sqrtf(e0 * e0 + e1 * e1);

    float gamma = g_gamma[b];
    float vals = expf(-(rb * rb) / (2.0f * 0.5f * 0.5f));
    vals *= (1.0f - expf(-(s * s) / (2.0f * gamma * gamma)));
    float f = fmaxf(0.0f, vals);
    out[((size_t)b * HH + gi) * WW + gj] = (f <= 0.0f) ? 1.0f : f;
}

extern "C" void kernel_launch(void* const* d_in, const int* in_sizes, int n_in,
                              void* d_out, int out_size) {
    const float* x       = (const float*)d_in[0];
    const float* to_gray = (const float*)d_in[1];
    float* out = (float*)d_out;

    dim3 block(TILE_X, TILE_Y);
    dim3 grid(WW / TILE_X, HH / TILE_Y, BATCH);

    reset_kernel<<<1, 32>>>();
    blur_kernel<<<grid, block>>>(x, to_gray);
    smax_kernel<<<grid, block>>>();
    gamma_kernel<<<1, 32>>>();
    final_kernel<<<grid, block>>>(out);
}

// round 3
// speedup vs baseline: 1.9636x; 1.9636x over previous
#include <cuda_runtime.h>
#include <math.h>

#define BATCH 16
#define HH 1024
#define WW 1024
#define TILE 32          // 32x32 output tile
#define NTH  256         // 32x8 threads, 4 rows/thread
#define RPT  4

// Blurred grayscale field g [B,H,W]
__device__ float g_buf[BATCH * HH * WW];
__device__ int   g_max_bits[BATCH];
__device__ float g_gamma[BATCH];

// 1D Gaussian weights / sum (fp32, == expf pipeline to <=1 ulp)
#define W0f 0.19800304f
#define W1f 0.20099547f
#define W2f 0.20200297f

__global__ void reset_kernel() {
    if (threadIdx.x < BATCH) g_max_bits[threadIdx.x] = 0;
}

// ---------------------------------------------------------------------------
// Edge-aware Hessian (torch.gradient semantics). p points at center, stride 36.
// ---------------------------------------------------------------------------
__device__ __forceinline__ void hessian_edge(const float* p, int gi, int gj,
                                             float& h00, float& h01, float& h11) {
    #define G(di, dj) p[(di)*36 + (dj)]
    float gxm, gx0, gxp;
    {
        int gr;
        gr = gi - 1;
        gxm = (gr == 0) ? (G(0,0) - G(-1,0))
            : (gi - 1 < 0) ? 0.0f
            : (gr == HH-1) ? (G(-1,0) - G(-2,0))
            : 0.5f * (G(0,0) - G(-2,0));
        gr = gi;
        gx0 = (gr == 0) ? (G(1,0) - G(0,0))
            : (gr == HH-1) ? (G(0,0) - G(-1,0))
            : 0.5f * (G(1,0) - G(-1,0));
        gr = gi + 1;
        gxp = (gr == 0) ? (G(2,0) - G(1,0))
            : (gr == HH-1) ? (G(1,0) - G(0,0))
            : (gi + 1 > HH-1) ? 0.0f
            : 0.5f * (G(2,0) - G(0,0));
    }
    h00 = (gi == 0) ? (gxp - gx0)
        : (gi == HH-1) ? (gx0 - gxm)
        : 0.5f * (gxp - gxm);

    float gxcm, gxc0, gxcp;
    {
        if (gi == 0) {
            gxcm = G(1,-1) - G(0,-1);
            gxc0 = G(1, 0) - G(0, 0);
            gxcp = G(1, 1) - G(0, 1);
        } else if (gi == HH-1) {
            gxcm = G(0,-1) - G(-1,-1);
            gxc0 = G(0, 0) - G(-1, 0);
            gxcp = G(0, 1) - G(-1, 1);
        } else {
            gxcm = 0.5f * (G(1,-1) - G(-1,-1));
            gxc0 = 0.5f * (G(1, 0) - G(-1, 0));
            gxcp = 0.5f * (G(1, 1) - G(-1, 1));
        }
    }
    h01 = (gj == 0) ? (gxcp - gxc0)
        : (gj == WW-1) ? (gxc0 - gxcm)
        : 0.5f * (gxcp - gxcm);

    float gym, gy0, gyp;
    {
        int gc;
        gc = gj - 1;
        gym = (gc == 0) ? (G(0,0) - G(0,-1))
            : (gj - 1 < 0) ? 0.0f
            : (gc == WW-1) ? (G(0,-1) - G(0,-2))
            : 0.5f * (G(0,0) - G(0,-2));
        gc = gj;
        gy0 = (gc == 0) ? (G(0,1) - G(0,0))
            : (gc == WW-1) ? (G(0,0) - G(0,-1))
            : 0.5f * (G(0,1) - G(0,-1));
        gc = gj + 1;
        gyp = (gc == 0) ? (G(0,2) - G(0,1))
            : (gc == WW-1) ? (G(0,1) - G(0,0))
            : (gj + 1 > WW-1) ? 0.0f
            : 0.5f * (G(0,2) - G(0,0));
    }
    h11 = (gj == 0) ? (gyp - gy0)
        : (gj == WW-1) ? (gy0 - gym)
        : 0.5f * (gyp - gym);
    #undef G
}

// Interior fast path — bit-identical to double central gradient (pow2 scalings)
__device__ __forceinline__ void hessian_fast(const float* p,
                                             float& h00, float& h01, float& h11) {
    #define G(di, dj) p[(di)*36 + (dj)]
    float A = G(2,0) - G(0,0);
    float B = G(0,0) - G(-2,0);
    h00 = 0.25f * (A - B);
    float C = G(0,2) - G(0,0);
    float D = G(0,0) - G(0,-2);
    h11 = 0.25f * (C - D);
    float P = G(1,1) - G(-1,1);
    float Q = G(1,-1) - G(-1,-1);
    h01 = 0.25f * (P - Q);
    #undef G
}

// ---------------------------------------------------------------------------
// PassA: gray -> separable blur (smem, halo 4) -> write g -> Hessian -> s-max
// ---------------------------------------------------------------------------
__global__ __launch_bounds__(NTH) void passA_kernel(const float* __restrict__ x,
                                                    const float* __restrict__ to_gray) {
    __shared__ float G[40 * 40];   // gray, halo 4
    __shared__ float Hh[40 * 36];  // horizontally blurred (cols -2..33)
    __shared__ float Gg[36 * 36];  // fully blurred (rows/cols -2..33)
    __shared__ float red[NTH / 32];

    const int b  = blockIdx.z;
    const int bx = blockIdx.x * TILE;
    const int by = blockIdx.y * TILE;
    const int tid = threadIdx.x;
    const int tx = tid & 31, ty = tid >> 5;

    const float c0 = to_gray[0], c1 = to_gray[1], c2 = to_gray[2];
    const float* xb = x + (size_t)b * 3 * HH * WW;

    // Gray tile load (zero outside image; SAME conv zero-pads)
    {
        int r = tid / 40, c = tid % 40;              // 256 = 6*40 + 16
        for (int idx = tid; idx < 1600; idx += NTH) {
            int gi = by + r - 4, gj = bx + c - 4;
            float v = 0.0f;
            if (gi >= 0 && gi < HH && gj >= 0 && gj < WW) {
                size_t off = (size_t)gi * WW + gj;
                v = c0 * xb[off] + c1 * xb[off + (size_t)HH * WW]
                                 + c2 * xb[off + 2 * (size_t)HH * WW];
            }
            G[r * 40 + c] = v;
            r += 6; c += 16; if (c >= 40) { c -= 40; ++r; }
        }
    }
    __syncthreads();

    // Horizontal blur: 40 rows x 36 cols
    {
        int r = tid / 36, c = tid % 36;              // 256 = 7*36 + 4
        for (int idx = tid; idx < 1440; idx += NTH) {
            const float* p = &G[r * 40 + c];
            Hh[r * 36 + c] = W0f*p[0] + W1f*p[1] + W2f*p[2] + W1f*p[3] + W0f*p[4];
            r += 7; c += 4; if (c >= 36) { c -= 36; ++r; }
        }
    }
    __syncthreads();

    // Vertical blur: 36 x 36
    {
        int r = tid / 36, c = tid % 36;
        for (int idx = tid; idx < 1296; idx += NTH) {
            const float* p = &Hh[r * 36 + c];
            Gg[r * 36 + c] = W0f*p[0] + W1f*p[36] + W2f*p[72] + W1f*p[108] + W0f*p[144];
            r += 7; c += 4; if (c >= 36) { c -= 36; ++r; }
        }
    }
    __syncthreads();

    // Write g + Hessian + s, per-block max
    const bool edge = (bx == 0) || (by == 0) || (bx + TILE == WW) || (by + TILE == HH);
    float smax = 0.0f;
    float* gb = g_buf + (size_t)b * HH * WW;

    #pragma unroll
    for (int k = 0; k < RPT; k++) {
        const int row = ty + k * 8;                 // 0..31
        const int gi = by + row, gj = bx + tx;
        const float* p = &Gg[(row + 2) * 36 + (tx + 2)];
        gb[(size_t)gi * WW + gj] = p[0];

        float h00, h01, h11;
        if (!edge) hessian_fast(p, h00, h01, h11);
        else       hessian_edge(p, gi, gj, h00, h01, h11);

        float mean = 0.5f * (h00 + h11);
        float dif  = 0.5f * (h00 - h11);
        float disc = sqrtf(dif * dif + h01 * h01);
        float e0 = mean - disc, e1 = mean + disc;
        float s = sqrtf(e0 * e0 + e1 * e1);
        smax = fmaxf(smax, s);
    }

    #pragma unroll
    for (int off = 16; off > 0; off >>= 1)
        smax = fmaxf(smax, __shfl_xor_sync(0xffffffffu, smax, off));
    if ((tid & 31) == 0) red[tid >> 5] = smax;
    __syncthreads();
    if (tid == 0) {
        float m = red[0];
        #pragma unroll
        for (int i = 1; i < NTH / 32; i++) m = fmaxf(m, red[i]);
        atomicMax(&g_max_bits[b], __float_as_int(m));  // s >= 0
    }
}

__global__ void gamma_kernel() {
    int i = threadIdx.x;
    float m = (i < BATCH) ? __int_as_float(g_max_bits[i]) : 0.0f;
    unsigned any = __ballot_sync(0xffffffffu, (i < BATCH) && (m != 0.0f));
    if (i < BATCH) g_gamma[i] = (any == 0u) ? 1.0f : 0.5f * m;
}

// ---------------------------------------------------------------------------
// PassB: read g (halo 2), Hessian, eigen order, final response
// ---------------------------------------------------------------------------
__global__ __launch_bounds__(NTH) void passB_kernel(float* __restrict__ out) {
    __shared__ float Gg[36 * 36];

    const int b  = blockIdx.z;
    const int bx = blockIdx.x * TILE;
    const int by = blockIdx.y * TILE;
    const int tid = threadIdx.x;
    const int tx = tid & 31, ty = tid >> 5;

    const float* gb = g_buf + (size_t)b * HH * WW;
    {
        int r = tid / 36, c = tid % 36;
        for (int idx = tid; idx < 1296; idx += NTH) {
            int gi = by + r - 2; gi = gi < 0 ? 0 : (gi > HH-1 ? HH-1 : gi);
            int gj = bx + c - 2; gj = gj < 0 ? 0 : (gj > WW-1 ? WW-1 : gj);
            Gg[r * 36 + c] = gb[(size_t)gi * WW + gj];
            r += 7; c += 4; if (c >= 36) { c -= 36; ++r; }
        }
    }
    __syncthreads();

    const bool edge = (bx == 0) || (by == 0) || (bx + TILE == WW) || (by + TILE == HH);
    const float gamma = g_gamma[b];
    const float sinv = -1.0f / (2.0f * gamma * gamma);

    #pragma unroll
    for (int k = 0; k < RPT; k++) {
        const int row = ty + k * 8;
        const int gi = by + row, gj = bx + tx;
        const float* p = &Gg[(row + 2) * 36 + (tx + 2)];

        float h00, h01, h11;
        if (!edge) hessian_fast(p, h00, h01, h11);
        else       hessian_edge(p, gi, gj, h00, h01, h11);

        float mean = 0.5f * (h00 + h11);
        float dif  = 0.5f * (h00 - h11);
        float disc = sqrtf(dif * dif + h01 * h01);
        float e0 = mean - disc, e1 = mean + disc;

        bool swap = fabsf(e1) < fabsf(e0);
        float lam1 = swap ? e1 : e0;
        float lam2 = fmaxf(swap ? e0 : e1, 1e-10f);
        float rb = fabsf(lam1) / lam2;
        float s  = sqrtf(e0 * e0 + e1 * e1);

        float vals = expf(-2.0f * rb * rb);          // -(rb^2)/(2*0.5*0.5), /0.5 exact
        vals *= (1.0f - expf(s * s * sinv));
        float f = fmaxf(0.0f, vals);
        out[((size_t)b * HH + gi) * WW + gj] = (f <= 0.0f) ? 1.0f : f;
    }
}

extern "C" void kernel_launch(void* const* d_in, const int* in_sizes, int n_in,
                              void* d_out, int out_size) {
    const float* x       = (const float*)d_in[0];
    const float* to_gray = (const float*)d_in[1];
    float* out = (float*)d_out;

    dim3 block(NTH);
    dim3 grid(WW / TILE, HH / TILE, BATCH);

    reset_kernel<<<1, 32>>>();
    passA_kernel<<<grid, block>>>(x, to_gray);
    gamma_kernel<<<1, 32>>>();
    passB_kernel<<<grid, block>>>(out);
}

// round 5
// speedup vs baseline: 2.8528x; 1.4528x over previous
#include <cuda_runtime.h>
#include <math.h>

#define BATCH 16
#define HH 1024
#define WW 1024
#define PLANE (HH * WW)
#define TX64 64
#define TY32 32
#define NTH  256

// Blurred grayscale field g [B,H,W]
__device__ float g_buf[BATCH * HH * WW];
__device__ int   g_max_bits[BATCH];
__device__ float g_gamma[BATCH];

#define W0f 0.19800304f
#define W1f 0.20099547f
#define W2f 0.20200297f

__global__ void reset_kernel() {
    if (threadIdx.x < BATCH) g_max_bits[threadIdx.x] = 0;
}

__global__ void gamma_kernel() {
    int i = threadIdx.x;
    float m = (i < BATCH) ? __int_as_float(g_max_bits[i]) : 0.0f;
    unsigned any = __ballot_sync(0xffffffffu, (i < BATCH) && (m != 0.0f));
    if (i < BATCH) g_gamma[i] = (any == 0u) ? 1.0f : 0.5f * m;
}

// ---------------------------------------------------------------------------
// Edge-aware Hessian from 13 register taps (torch.gradient semantics).
// Naming: u=row-1, d=row+1 (G(1,0)=d1 etc.), l/r along columns.
// ---------------------------------------------------------------------------
__device__ __forceinline__ void hessian_edge_regs(
    float c00, float u1, float u2, float d1, float d2,
    float l1, float l2, float r1, float r2,
    float ul, float ur, float dl, float dr,
    int gi, int gj, float& h00, float& h01, float& h11)
{
    float gxm, gx0, gxp;
    {
        int gr;
        gr = gi - 1;
        gxm = (gr == 0) ? (c00 - u1)
            : (gi - 1 < 0) ? 0.0f
            : (gr == HH-1) ? (u1 - u2)
            : 0.5f * (c00 - u2);
        gr = gi;
        gx0 = (gr == 0) ? (d1 - c00)
            : (gr == HH-1) ? (c00 - u1)
            : 0.5f * (d1 - u1);
        gr = gi + 1;
        gxp = (gr == 0) ? (d2 - d1)
            : (gr == HH-1) ? (d1 - c00)
            : (gi + 1 > HH-1) ? 0.0f
            : 0.5f * (d2 - c00);
    }
    h00 = (gi == 0) ? (gxp - gx0)
        : (gi == HH-1) ? (gx0 - gxm)
        : 0.5f * (gxp - gxm);

    float gxcm, gxc0, gxcp;
    {
        if (gi == 0) {
            gxcm = dl - l1;
            gxc0 = d1 - c00;
            gxcp = dr - r1;
        } else if (gi == HH-1) {
            gxcm = l1 - ul;
            gxc0 = c00 - u1;
            gxcp = r1 - ur;
        } else {
            gxcm = 0.5f * (dl - ul);
            gxc0 = 0.5f * (d1 - u1);
            gxcp = 0.5f * (dr - ur);
        }
    }
    h01 = (gj == 0) ? (gxcp - gxc0)
        : (gj == WW-1) ? (gxc0 - gxcm)
        : 0.5f * (gxcp - gxcm);

    float gym, gy0, gyp;
    {
        int gc;
        gc = gj - 1;
        gym = (gc == 0) ? (c00 - l1)
            : (gj - 1 < 0) ? 0.0f
            : (gc == WW-1) ? (l1 - l2)
            : 0.5f * (c00 - l2);
        gc = gj;
        gy0 = (gc == 0) ? (r1 - c00)
            : (gc == WW-1) ? (c00 - l1)
            : 0.5f * (r1 - l1);
        gc = gj + 1;
        gyp = (gc == 0) ? (r2 - r1)
            : (gc == WW-1) ? (r1 - c00)
            : (gj + 1 > WW-1) ? 0.0f
            : 0.5f * (r2 - c00);
    }
    h11 = (gj == 0) ? (gyp - gy0)
        : (gj == WW-1) ? (gy0 - gym)
        : 0.5f * (gyp - gym);
}

__device__ __forceinline__ float s_of(float h00, float h01, float h11) {
    float mean = 0.5f * (h00 + h11);
    float dif  = 0.5f * (h00 - h11);
    float disc = sqrtf(dif * dif + h01 * h01);
    float e0 = mean - disc, e1 = mean + disc;
    return sqrtf(e0 * e0 + e1 * e1);
}

__device__ __forceinline__ float response_of(float h00, float h01, float h11, float sinv) {
    float mean = 0.5f * (h00 + h11);
    float dif  = 0.5f * (h00 - h11);
    float disc = sqrtf(dif * dif + h01 * h01);
    float e0 = mean - disc, e1 = mean + disc;
    bool swap = fabsf(e1) < fabsf(e0);
    float lam1 = swap ? e1 : e0;
    float lam2 = fmaxf(swap ? e0 : e1, 1e-10f);
    float rb = __fdividef(fabsf(lam1), lam2);
    float s  = sqrtf(e0 * e0 + e1 * e1);
    float vals = __expf(-2.0f * rb * rb);
    vals *= (1.0f - __expf(s * s * sinv));
    float f = fmaxf(0.0f, vals);
    return (f <= 0.0f) ? 1.0f : f;
}

// ---------------------------------------------------------------------------
// PassA: gray -> separable blur (smem, f4) -> write g (f4) -> Hessian -> s-max
// Tile 64x32, halo 4. SA: gray 40x72, later reused as Gg 36x68. SB: Hh 40x68.
// ---------------------------------------------------------------------------
__global__ __launch_bounds__(NTH) void passA_kernel(const float* __restrict__ x,
                                                    const float* __restrict__ to_gray) {
    __shared__ __align__(16) float SA[40 * 72];   // gray (stride 72) -> Gg (stride 68)
    __shared__ __align__(16) float SB[40 * 68];   // Hh (stride 68)
    __shared__ float red[NTH / 32];

    const int b  = blockIdx.z;
    const int bx = blockIdx.x * TX64;
    const int by = blockIdx.y * TY32;
    const int tid = threadIdx.x;

    const float c0 = to_gray[0], c1 = to_gray[1], c2 = to_gray[2];
    const float* xb = x + (size_t)b * 3 * PLANE;

    // ---- gray tile: rows by-4..by+35 (40), cols bx-4..bx+67 (18 f4) ----
    {
        int r = tid / 18, c4 = tid % 18;
        for (int idx = tid; idx < 720; idx += NTH) {
            int gi = by + r - 4;
            int gj = bx + c4 * 4 - 4;
            float4 v = make_float4(0.f, 0.f, 0.f, 0.f);
            if (gi >= 0 && gi < HH && gj >= 0 && gj <= WW - 4) {
                size_t off = (size_t)gi * WW + gj;
                float4 p0 = *reinterpret_cast<const float4*>(xb + off);
                float4 p1 = *reinterpret_cast<const float4*>(xb + off + PLANE);
                float4 p2 = *reinterpret_cast<const float4*>(xb + off + 2 * PLANE);
                v.x = c0 * p0.x + c1 * p1.x + c2 * p2.x;
                v.y = c0 * p0.y + c1 * p1.y + c2 * p2.y;
                v.z = c0 * p0.z + c1 * p1.z + c2 * p2.z;
                v.w = c0 * p0.w + c1 * p1.w + c2 * p2.w;
            }
            *reinterpret_cast<float4*>(&SA[r * 72 + c4 * 4]) = v;
            r += 14; c4 += 4; if (c4 >= 18) { c4 -= 18; ++r; }
        }
    }
    __syncthreads();

    // ---- horizontal blur: 40 rows x 17 f4 (cols bx-2..bx+65) ----
    {
        int r = tid / 17, c4 = tid % 17;
        for (int idx = tid; idx < 680; idx += NTH) {
            const float* p = &SA[r * 72 + c4 * 4];
            float4 qa = *reinterpret_cast<const float4*>(p);
            float4 qb = *reinterpret_cast<const float4*>(p + 4);
            float q[8] = {qa.x, qa.y, qa.z, qa.w, qb.x, qb.y, qb.z, qb.w};
            float4 o;
            o.x = W0f*q[0] + W1f*q[1] + W2f*q[2] + W1f*q[3] + W0f*q[4];
            o.y = W0f*q[1] + W1f*q[2] + W2f*q[3] + W1f*q[4] + W0f*q[5];
            o.z = W0f*q[2] + W1f*q[3] + W2f*q[4] + W1f*q[5] + W0f*q[6];
            o.w = W0f*q[3] + W1f*q[4] + W2f*q[5] + W1f*q[6] + W0f*q[7];
            *reinterpret_cast<float4*>(&SB[r * 68 + c4 * 4]) = o;
            r += 15; c4 += 1; if (c4 >= 17) { c4 -= 17; ++r; }
        }
    }
    __syncthreads();

    // ---- vertical blur: 36 rows x 17 f4 into SA (Gg, stride 68) ----
    {
        int r = tid / 17, c4 = tid % 17;
        for (int idx = tid; idx < 612; idx += NTH) {
            const float* p = &SB[r * 68 + c4 * 4];
            float4 a0 = *reinterpret_cast<const float4*>(p);
            float4 a1 = *reinterpret_cast<const float4*>(p + 68);
            float4 a2 = *reinterpret_cast<const float4*>(p + 136);
            float4 a3 = *reinterpret_cast<const float4*>(p + 204);
            float4 a4 = *reinterpret_cast<const float4*>(p + 272);
            float4 o;
            o.x = W0f*a0.x + W1f*a1.x + W2f*a2.x + W1f*a3.x + W0f*a4.x;
            o.y = W0f*a0.y + W1f*a1.y + W2f*a2.y + W1f*a3.y + W0f*a4.y;
            o.z = W0f*a0.z + W1f*a1.z + W2f*a2.z + W1f*a3.z + W0f*a4.z;
            o.w = W0f*a0.w + W1f*a1.w + W2f*a2.w + W1f*a3.w + W0f*a4.w;
            *reinterpret_cast<float4*>(&SA[r * 68 + c4 * 4]) = o;
            r += 15; c4 += 1; if (c4 >= 17) { c4 -= 17; ++r; }
        }
    }
    __syncthreads();

    // ---- tail: write g (f4) + Hessian + s, per-block max ----
    // Gg (in SA): row r <-> gi = by-2+r, col c <-> gj = bx-2+c (68 cols valid)
    const bool edge = (bx == 0) || (by == 0) || (bx + TX64 == WW) || (by + TY32 == HH);
    const int tx = tid & 15;        // f4 column group: gj = bx + tx*4
    const int ty = tid >> 4;        // row 0..15, rows ty and ty+16
    float smax = 0.0f;
    float* gb = g_buf + (size_t)b * PLANE;

    #pragma unroll
    for (int k = 0; k < 2; k++) {
        const int row = ty + 16 * k;              // 0..31
        const int gi = by + row;
        const int c0i = tx * 4;                   // Gg col base; a[j] <-> gj offset j-2
        const float* Rc = &SA[(row + 2) * 68 + c0i];

        float4 A0 = *reinterpret_cast<const float4*>(Rc);
        float4 A1 = *reinterpret_cast<const float4*>(Rc + 4);
        float a[8] = {A0.x, A0.y, A0.z, A0.w, A1.x, A1.y, A1.z, A1.w};

        // g write: center values a[2..5]
        *reinterpret_cast<float4*>(gb + (size_t)gi * WW + bx + c0i) =
            make_float4(a[2], a[3], a[4], a[5]);

        if (!edge) {
            const float* Ru = Rc - 68;
            const float* Rd = Rc + 68;
            const float* Rt = Rc - 136;
            const float* Rb2 = Rc + 136;
            float4 U0 = *reinterpret_cast<const float4*>(Ru);
            float4 U1 = *reinterpret_cast<const float4*>(Ru + 4);
            float4 D0 = *reinterpret_cast<const float4*>(Rd);
            float4 D1 = *reinterpret_cast<const float4*>(Rd + 4);
            float4 T0 = *reinterpret_cast<const float4*>(Rt);
            float4 T1 = *reinterpret_cast<const float4*>(Rt + 4);
            float4 B0 = *reinterpret_cast<const float4*>(Rb2);
            float4 B1 = *reinterpret_cast<const float4*>(Rb2 + 4);
            float u[8] = {U0.x, U0.y, U0.z, U0.w, U1.x, U1.y, U1.z, U1.w};
            float d[8] = {D0.x, D0.y, D0.z, D0.w, D1.x, D1.y, D1.z, D1.w};
            float t[8] = {T0.x, T0.y, T0.z, T0.w, T1.x, T1.y, T1.z, T1.w};
            float bb[8] = {B0.x, B0.y, B0.z, B0.w, B1.x, B1.y, B1.z, B1.w};

            #pragma unroll
            for (int l = 0; l < 4; l++) {
                float c00 = a[2 + l];
                float A = bb[2 + l] - c00;        // G(2,0)-G(0,0)
                float B = c00 - t[2 + l];         // G(0,0)-G(-2,0)
                float h00 = 0.25f * (A - B);
                float C = a[4 + l] - c00;
                float D = c00 - a[l];
                float h11 = 0.25f * (C - D);
                float P = d[3 + l] - u[3 + l];    // G(1,1)-G(-1,1)
                float Q = d[1 + l] - u[1 + l];    // G(1,-1)-G(-1,-1)
                float h01 = 0.25f * (P - Q);
                smax = fmaxf(smax, s_of(h00, h01, h11));
            }
        } else {
            #pragma unroll
            for (int l = 0; l < 4; l++) {
                const int gj = bx + c0i + l;
                const float* p = &SA[(row + 2) * 68 + (c0i + l + 2)];
                float h00, h01, h11;
                hessian_edge_regs(p[0], p[-68], p[-136], p[68], p[136],
                                  p[-1], p[-2], p[1], p[2],
                                  p[-69], p[-67], p[67], p[69],
                                  gi, gj, h00, h01, h11);
                smax = fmaxf(smax, s_of(h00, h01, h11));
            }
        }
    }

    #pragma unroll
    for (int off = 16; off > 0; off >>= 1)
        smax = fmaxf(smax, __shfl_xor_sync(0xffffffffu, smax, off));
    if ((tid & 31) == 0) red[tid >> 5] = smax;
    __syncthreads();
    if (tid == 0) {
        float m = red[0];
        #pragma unroll
        for (int i = 1; i < NTH / 32; i++) m = fmaxf(m, red[i]);
        atomicMax(&g_max_bits[b], __float_as_int(m));  // s >= 0
    }
}

// ---------------------------------------------------------------------------
// PassB: direct global f4 loads (no smem), Hessian, final response
// ---------------------------------------------------------------------------
__global__ __launch_bounds__(NTH) void passB_kernel(float* __restrict__ out) {
    const int b  = blockIdx.z;
    const int bx = blockIdx.x * TX64;
    const int by = blockIdx.y * TY32;
    const int tid = threadIdx.x;
    const int tx = tid & 15;
    const int ty = tid >> 4;

    const float* gb = g_buf + (size_t)b * PLANE;
    const bool edge = (bx == 0) || (by == 0) || (bx + TX64 == WW) || (by + TY32 == HH);
    const float gamma = g_gamma[b];
    const float sinv = -1.0f / (2.0f * gamma * gamma);
    float* ob = out + (size_t)b * PLANE;

    #pragma unroll
    for (int k = 0; k < 2; k++) {
        const int row = ty + 16 * k;
        const int gi = by + row;
        const int gj0 = bx + tx * 4;
        const size_t base = (size_t)gi * WW + gj0;

        if (!edge) {
            float4 A0 = __ldg(reinterpret_cast<const float4*>(gb + base - 4));
            float4 A1 = __ldg(reinterpret_cast<const float4*>(gb + base));
            float4 A2 = __ldg(reinterpret_cast<const float4*>(gb + base + 4));
            float4 U0 = __ldg(reinterpret_cast<const float4*>(gb + base - WW - 4));
            float4 U1 = __ldg(reinterpret_cast<const float4*>(gb + base - WW));
            float4 U2 = __ldg(reinterpret_cast<const float4*>(gb + base - WW + 4));
            float4 D0 = __ldg(reinterpret_cast<const float4*>(gb + base + WW - 4));
            float4 D1 = __ldg(reinterpret_cast<const float4*>(gb + base + WW));
            float4 D2 = __ldg(reinterpret_cast<const float4*>(gb + base + WW + 4));
            float4 Tt = __ldg(reinterpret_cast<const float4*>(gb + base - 2 * WW));
            float4 Bb = __ldg(reinterpret_cast<const float4*>(gb + base + 2 * WW));

            // a[j] <-> gj0 + (j-4)
            float a[12] = {A0.x, A0.y, A0.z, A0.w, A1.x, A1.y, A1.z, A1.w, A2.x, A2.y, A2.z, A2.w};
            float u[12] = {U0.x, U0.y, U0.z, U0.w, U1.x, U1.y, U1.z, U1.w, U2.x, U2.y, U2.z, U2.w};
            float d[12] = {D0.x, D0.y, D0.z, D0.w, D1.x, D1.y, D1.z, D1.w, D2.x, D2.y, D2.z, D2.w};
            float t[4] = {Tt.x, Tt.y, Tt.z, Tt.w};
            float bm[4] = {Bb.x, Bb.y, Bb.z, Bb.w};

            float4 o;
            float* op = &o.x;
            #pragma unroll
            for (int l = 0; l < 4; l++) {
                float c00 = a[4 + l];
                float A = bm[l] - c00;
                float B = c00 - t[l];
                float h00 = 0.25f * (A - B);
                float C = a[6 + l] - c00;
                float D = c00 - a[2 + l];
                float h11 = 0.25f * (C - D);
                float P = d[5 + l] - u[5 + l];
                float Q = d[3 + l] - u[3 + l];
                float h01 = 0.25f * (P - Q);
                op[l] = response_of(h00, h01, h11, sinv);
            }
            *reinterpret_cast<float4*>(ob + base) = o;
        } else {
            float4 o;
            float* op = &o.x;
            #pragma unroll
            for (int l = 0; l < 4; l++) {
                const int gj = gj0 + l;
                #define CL(v, lim) ((v) < 0 ? 0 : ((v) > (lim) ? (lim) : (v)))
                #define TAP(di, dj) __ldg(gb + (size_t)CL(gi + (di), HH-1) * WW + CL(gj + (dj), WW-1))
                float c00 = TAP(0,0);
                float u1 = TAP(-1,0), u2 = TAP(-2,0), d1 = TAP(1,0), d2 = TAP(2,0);
                float l1 = TAP(0,-1), l2 = TAP(0,-2), r1 = TAP(0,1), r2 = TAP(0,2);
                float ul = TAP(-1,-1), ur = TAP(-1,1), dl = TAP(1,-1), dr = TAP(1,1);
                #undef TAP
                #undef CL
                float h00, h01, h11;
                hessian_edge_regs(c00, u1, u2, d1, d2, l1, l2, r1, r2,
                                  ul, ur, dl, dr, gi, gj, h00, h01, h11);
                op[l] = response_of(h00, h01, h11, sinv);
            }
            *reinterpret_cast<float4*>(ob + base) = o;
        }
    }
}

extern "C" void kernel_launch(void* const* d_in, const int* in_sizes, int n_in,
                              void* d_out, int out_size) {
    const float* x       = (const float*)d_in[0];
    const float* to_gray = (const float*)d_in[1];
    float* out = (float*)d_out;

    dim3 block(NTH);
    dim3 grid(WW / TX64, HH / TY32, BATCH);

    reset_kernel<<<1, 32>>>();
    passA_kernel<<<grid, block>>>(x, to_gray);
    gamma_kernel<<<1, 32>>>();
    passB_kernel<<<grid, block>>>(out);
}